// round 1
// baseline (speedup 1.0000x reference)
#include <cuda_runtime.h>
#include <math.h>

#define B_ 8
#define N_ 256
#define F_ 59
#define C_ 128

// ---------------- device scratch (no allocations allowed) ----------------
__device__ float g_v[B_*N_*C_];      // values  x @ W_lin^T
__device__ float g_tsrc[B_*N_*C_];   // attn_w' @ (x @ W_src^T)
__device__ float g_tdst[B_*N_*C_];   // attn_w' @ (x @ W_dst^T)  (+ folded bias)
__device__ float g_awf[C_*C_];       // BN-folded attn_w (row-scaled)
__device__ float g_pwf[C_*6];        // BN-folded pos_w
__device__ float g_pbf[C_];          // BN-folded pos bias
__device__ float g_b2f[C_];          // BN-folded attn bias

// ---------------- kernel A: fold BN into weights ----------------
__global__ void fold_kernel(const float* __restrict__ pos_w, const float* __restrict__ pos_b,
                            const float* __restrict__ pg, const float* __restrict__ pb,
                            const float* __restrict__ pm, const float* __restrict__ pv,
                            const float* __restrict__ attn_w, const float* __restrict__ attn_b,
                            const float* __restrict__ ag, const float* __restrict__ ab,
                            const float* __restrict__ am, const float* __restrict__ av)
{
    int c = threadIdx.x;  // 128 threads
    float s1 = pg[c] * rsqrtf(pv[c] + 1e-5f);
    g_pbf[c] = pos_b[c] * s1 + pb[c] - pm[c] * s1;
#pragma unroll
    for (int k = 0; k < 6; k++) g_pwf[c*6+k] = pos_w[c*6+k] * s1;

    float s2 = ag[c] * rsqrtf(av[c] + 1e-5f);
    g_b2f[c] = attn_b[c] * s2 + ab[c] - am[c] * s2;
    for (int k = 0; k < C_; k++) g_awf[c*C_+k] = attn_w[c*C_+k] * s2;
}

// ---------------- kernel B: per-node precompute ----------------
// grid = 128 blocks (b in [0,8) x 16 chunks of 16 nodes), 256 threads.
__global__ void precompute_kernel(const float* __restrict__ x,
                                  const float* __restrict__ Wl,
                                  const float* __restrict__ Ws,
                                  const float* __restrict__ Wd)
{
    extern __shared__ float sh[];
    float* s_wl = sh;                 // F_*C_
    float* s_ws = s_wl + F_*C_;
    float* s_wd = s_ws + F_*C_;
    float* s_aw = s_wd + F_*C_;       // 128*129 (padded)
    float* s_x  = s_aw + 128*129;     // 2*64
    float* s_as = s_x + 128;          // 2*128
    float* s_ad = s_as + 256;         // 2*128

    int t = threadIdx.x;
    int bb = blockIdx.x >> 4;
    int n0 = (blockIdx.x & 15) * 16;

    for (int idx = t; idx < F_*C_; idx += 256) {
        s_wl[idx] = Wl[idx]; s_ws[idx] = Ws[idx]; s_wd[idx] = Wd[idx];
    }
    for (int idx = t; idx < C_*C_; idx += 256)
        s_aw[(idx >> 7) * 129 + (idx & 127)] = g_awf[idx];

    int half = t >> 7, c = t & 127;
    float b2 = g_b2f[c];
    __syncthreads();

    for (int it = 0; it < 8; it++) {
        int n = n0 + it*2 + half;
        if (c < F_) s_x[half*64 + c] = x[(bb*N_ + n)*F_ + c];
        __syncthreads();

        float v = 0.f, as = 0.f, ad = 0.f;
        const float* xs = s_x + half*64;
        for (int f = 0; f < F_; f++) {
            float xv = xs[f];
            v  = fmaf(xv, s_wl[c*F_+f], v);
            as = fmaf(xv, s_ws[c*F_+f], as);
            ad = fmaf(xv, s_wd[c*F_+f], ad);
        }
        g_v[(bb*N_ + n)*C_ + c] = v;
        s_as[half*128 + c] = as;
        s_ad[half*128 + c] = ad;
        __syncthreads();

        float ts = 0.f, td = 0.f;
        const float* awr = s_aw + c*129;
        const float* asr = s_as + half*128;
        const float* adr = s_ad + half*128;
        for (int k = 0; k < C_; k++) {
            float w = awr[k];
            ts = fmaf(w, asr[k], ts);
            td = fmaf(w, adr[k], td);
        }
        g_tsrc[(bb*N_ + n)*C_ + c] = ts;
        g_tdst[(bb*N_ + n)*C_ + c] = td + b2;
        __syncthreads();
    }
}

// ---------------- kernel C: fused attention per (b, i) ----------------
// grid = 2048, block = 256 (thread = (half h, channel d)).
__global__ void __launch_bounds__(256, 2)
main_kernel(const float* __restrict__ pos, const float* __restrict__ nrm,
            const float* __restrict__ rptr, float* __restrict__ out)
{
    extern __shared__ float sh[];
    float* s_aw    = sh;                    // 128*129 = 16512
    float* s_delta = s_aw + 128*129;        // 32*128  = 4096
    float* s_relf  = s_delta + 32*128;      // 32*8    = 256
    float* s_red   = s_relf + 32*8;         // 3*128   = 384
    float* s_geo   = s_red + 384;           // 8
    int*   s_list  = (int*)(s_geo + 8);     // 256
    int*   s_cnt   = s_list + 256;          // 1

    const int bi = blockIdx.x;
    const int b = bi >> 8, i = bi & 255;
    const int t = threadIdx.x;
    const int d = t & 127, h = t >> 7;

    for (int idx = t; idx < C_*C_; idx += 256)
        s_aw[(idx >> 7) * 129 + (idx & 127)] = g_awf[idx];
    if (t == 0) *s_cnt = 0;
    if (t < 3) {
        s_geo[t]     = pos[(b*N_ + i)*3 + t];
        s_geo[t + 3] = nrm[(b*N_ + i)*3 + t];
    }
    __syncthreads();

    // radius: 'r' may arrive as int32/int64 or float32
    float rr;
    {
        int iv = *(const int*)rptr;
        rr = (iv > 0 && iv < 1000000) ? (float)iv : *rptr;
    }
    {
        int j = t;  // 256 threads == 256 candidate neighbors
        float dx = s_geo[0] - pos[(b*N_ + j)*3 + 0];
        float dy = s_geo[1] - pos[(b*N_ + j)*3 + 1];
        float dz = s_geo[2] - pos[(b*N_ + j)*3 + 2];
        float dist2 = dx*dx + dy*dy + dz*dz;
        if (dist2 <= rr*rr) {
            int p = atomicAdd(s_cnt, 1);
            s_list[p] = j;
        }
    }
    __syncthreads();
    const int nv = *s_cnt;

    // per-thread folded pos weights + t_dst
    float pw[6];
#pragma unroll
    for (int k = 0; k < 6; k++) pw[k] = g_pwf[d*6+k];
    const float pbv  = g_pbf[d];
    const float tdst = g_tdst[bi*C_ + d];
    const float* vbase = g_v    + (size_t)(b*N_)*C_;
    const float* tsb   = g_tsrc + (size_t)(b*N_)*C_;

    float m = -1e30f, l = 0.f, o = 0.f;

    for (int base = 0; base < nv; base += 32) {
        const int cnt = min(32, nv - base);

        // stage relative geometry for this tile
        if (t < 32) {
            int row = t;
            if (row < cnt) {
                int j = s_list[base + row];
                const float* pj = pos + (b*N_ + j)*3;
                const float* nj = nrm + (b*N_ + j)*3;
                s_relf[row*8 + 0] = s_geo[0] - pj[0];
                s_relf[row*8 + 1] = s_geo[1] - pj[1];
                s_relf[row*8 + 2] = s_geo[2] - pj[2];
                s_relf[row*8 + 3] = s_geo[3] - nj[0];
                s_relf[row*8 + 4] = s_geo[4] - nj[1];
                s_relf[row*8 + 5] = s_geo[5] - nj[2];
            }
        }
        __syncthreads();

        // delta[row][d] = relu(relf . pw' + pb')
        for (int r2 = h; r2 < 32; r2 += 2) {
            float dv = 0.f;
            if (r2 < cnt) {
                const float* rf = s_relf + r2*8;
                dv = pbv;
#pragma unroll
                for (int k = 0; k < 6; k++) dv = fmaf(rf[k], pw[k], dv);
                dv = fmaxf(dv, 0.f);
            }
            s_delta[r2*128 + d] = dv;
        }
        __syncthreads();

        // matvec: acc[q] = attn_w'[d,:] . delta[h*16+q, :]
        float acc[16];
#pragma unroll
        for (int q = 0; q < 16; q++) acc[q] = 0.f;
        const float* awr = s_aw + d*129;
        const float* dlt = s_delta + (h*16)*128;
        for (int c0 = 0; c0 < 128; c0 += 4) {
            float w0 = awr[c0], w1 = awr[c0+1], w2 = awr[c0+2], w3 = awr[c0+3];
#pragma unroll
            for (int q = 0; q < 16; q++) {
                const float4 dv = *(const float4*)(dlt + q*128 + c0);
                acc[q] = fmaf(w0, dv.x, fmaf(w1, dv.y, fmaf(w2, dv.z, fmaf(w3, dv.w, acc[q]))));
            }
        }

        // epilogue: online softmax + weighted value accumulation
#pragma unroll
        for (int q = 0; q < 16; q++) {
            int row = h*16 + q;
            if (row < cnt) {
                int j = s_list[base + row];
                float z = acc[q] + tdst - tsb[j*C_ + d];
                float s = fmaxf(z, 0.f);
                float val = vbase[j*C_ + d] + s_delta[row*128 + d];
                float nm = fmaxf(m, s);
                float ea = __expf(m - nm), ep = __expf(s - nm);
                l = l*ea + ep;
                o = fmaf(o, ea, ep*val);
                m = nm;
            }
        }
        // no extra sync needed: next tile's first __syncthreads() (after relf
        // staging) orders these s_delta reads before the next delta writes.
    }

    // merge the two halves' online-softmax states
    if (h == 0) { s_red[d] = m; s_red[128 + d] = l; s_red[256 + d] = o; }
    __syncthreads();
    if (h == 1) {
        float M  = fmaxf(m, s_red[d]);
        float e0 = __expf(s_red[d] - M), e1 = __expf(m - M);
        float L  = s_red[128 + d]*e0 + l*e1;
        float O  = s_red[256 + d]*e0 + o*e1;
        out[bi*C_ + d] = O / L;
    }
}

// ---------------- launch ----------------
extern "C" void kernel_launch(void* const* d_in, const int* in_sizes, int n_in,
                              void* d_out, int out_size)
{
    const float* x      = (const float*)d_in[0];
    const float* pos    = (const float*)d_in[1];
    const float* normal = (const float*)d_in[2];
    const float* W_lin  = (const float*)d_in[3];
    const float* W_src  = (const float*)d_in[4];
    const float* W_dst  = (const float*)d_in[5];
    const float* pos_w  = (const float*)d_in[6];
    const float* pos_b  = (const float*)d_in[7];
    const float* pbn_g  = (const float*)d_in[8];
    const float* pbn_b  = (const float*)d_in[9];
    const float* pbn_m  = (const float*)d_in[10];
    const float* pbn_v  = (const float*)d_in[11];
    const float* attn_w = (const float*)d_in[12];
    const float* attn_b = (const float*)d_in[13];
    const float* abn_g  = (const float*)d_in[14];
    const float* abn_b  = (const float*)d_in[15];
    const float* abn_m  = (const float*)d_in[16];
    const float* abn_v  = (const float*)d_in[17];
    const float* rptr   = (const float*)d_in[18];
    float* out = (float*)d_out;

    const size_t smemB = (size_t)(3*F_*C_ + 128*129 + 128 + 256 + 256) * sizeof(float);
    const size_t smemC = (size_t)(128*129 + 32*128 + 32*8 + 384 + 8) * sizeof(float)
                       + (size_t)257 * sizeof(int);

    static bool attr_done = false;
    // setting an attribute is idempotent & deterministic; do it every call
    cudaFuncSetAttribute(precompute_kernel, cudaFuncAttributeMaxDynamicSharedMemorySize, (int)smemB);
    cudaFuncSetAttribute(main_kernel,       cudaFuncAttributeMaxDynamicSharedMemorySize, (int)smemC);
    (void)attr_done; (void)in_sizes; (void)n_in; (void)out_size;

    fold_kernel<<<1, 128>>>(pos_w, pos_b, pbn_g, pbn_b, pbn_m, pbn_v,
                            attn_w, attn_b, abn_g, abn_b, abn_m, abn_v);
    precompute_kernel<<<128, 256, smemB>>>(x, W_lin, W_src, W_dst);
    main_kernel<<<B_*N_, 256, smemC>>>(pos, normal, rptr, out);
}

// round 2
// speedup vs baseline: 1.5933x; 1.5933x over previous
#include <cuda_runtime.h>
#include <math.h>

#define B_ 8
#define N_ 256
#define F_ 59
#define C_ 128

// ---------------- device scratch ----------------
__device__ float g_v[B_*N_*C_];      // values  x @ W_lin^T
__device__ float g_tsrc[B_*N_*C_];   // attn_w' @ (x @ W_src^T)
__device__ float g_tdst[B_*N_*C_];   // attn_w' @ (x @ W_dst^T) + folded bias
__device__ float g_awf[C_*C_];       // BN-folded attn_w, row-major [d][c]
__device__ float g_awfT[C_*C_];      // transposed [c][d]
__device__ float g_pwf[C_*6];        // BN-folded pos_w
__device__ float g_pbf[C_];          // BN-folded pos bias
__device__ float g_b2f[C_];          // BN-folded attn bias

// ---------------- packed f32x2 helpers ----------------
__device__ __forceinline__ unsigned long long dup2(float x) {
    unsigned long long r;
    asm("mov.b64 %0, {%1, %1};" : "=l"(r) : "r"(__float_as_uint(x)));
    return r;
}
__device__ __forceinline__ void fma2(unsigned long long& a,
                                     unsigned long long x, unsigned long long y) {
    asm("fma.rn.f32x2 %0, %1, %2, %0;" : "+l"(a) : "l"(x), "l"(y));
}
__device__ __forceinline__ void unpack2(unsigned long long a, float& lo, float& hi) {
    unsigned int l_, h_;
    asm("mov.b64 {%0, %1}, %2;" : "=r"(l_), "=r"(h_) : "l"(a));
    lo = __uint_as_float(l_); hi = __uint_as_float(h_);
}

// ---------------- kernel A: fold BN into weights (parallel) ----------------
// grid = 128 (one block per output channel c), 128 threads.
__global__ void fold_kernel(const float* __restrict__ pos_w, const float* __restrict__ pos_b,
                            const float* __restrict__ pg, const float* __restrict__ pb,
                            const float* __restrict__ pm, const float* __restrict__ pv,
                            const float* __restrict__ attn_w, const float* __restrict__ attn_b,
                            const float* __restrict__ ag, const float* __restrict__ ab,
                            const float* __restrict__ am, const float* __restrict__ av)
{
    int c = blockIdx.x;
    int k = threadIdx.x;
    float s2 = ag[c] * rsqrtf(av[c] + 1e-5f);
    float w = attn_w[c*C_ + k] * s2;
    g_awf[c*C_ + k]  = w;
    g_awfT[k*C_ + c] = w;
    if (k == 0) {
        g_b2f[c] = attn_b[c] * s2 + ab[c] - am[c] * s2;
        float s1 = pg[c] * rsqrtf(pv[c] + 1e-5f);
        g_pbf[c] = pos_b[c] * s1 + pb[c] - pm[c] * s1;
#pragma unroll
        for (int q = 0; q < 6; q++) g_pwf[c*6 + q] = pos_w[c*6 + q] * s1;
    }
}

// ---------------- kernel B: per-node precompute (unchanged) ----------------
__global__ void precompute_kernel(const float* __restrict__ x,
                                  const float* __restrict__ Wl,
                                  const float* __restrict__ Ws,
                                  const float* __restrict__ Wd)
{
    extern __shared__ float sh[];
    float* s_wl = sh;                 // F_*C_
    float* s_ws = s_wl + F_*C_;
    float* s_wd = s_ws + F_*C_;
    float* s_aw = s_wd + F_*C_;       // 128*129 (padded)
    float* s_x  = s_aw + 128*129;     // 2*64
    float* s_as = s_x + 128;          // 2*128
    float* s_ad = s_as + 256;         // 2*128

    int t = threadIdx.x;
    int bb = blockIdx.x >> 4;
    int n0 = (blockIdx.x & 15) * 16;

    for (int idx = t; idx < F_*C_; idx += 256) {
        s_wl[idx] = Wl[idx]; s_ws[idx] = Ws[idx]; s_wd[idx] = Wd[idx];
    }
    for (int idx = t; idx < C_*C_; idx += 256)
        s_aw[(idx >> 7) * 129 + (idx & 127)] = g_awf[idx];

    int half = t >> 7, c = t & 127;
    float b2 = g_b2f[c];
    __syncthreads();

    for (int it = 0; it < 8; it++) {
        int n = n0 + it*2 + half;
        if (c < F_) s_x[half*64 + c] = x[(bb*N_ + n)*F_ + c];
        __syncthreads();

        float v = 0.f, as = 0.f, ad = 0.f;
        const float* xs = s_x + half*64;
        for (int f = 0; f < F_; f++) {
            float xv = xs[f];
            v  = fmaf(xv, s_wl[c*F_+f], v);
            as = fmaf(xv, s_ws[c*F_+f], as);
            ad = fmaf(xv, s_wd[c*F_+f], ad);
        }
        g_v[(bb*N_ + n)*C_ + c] = v;
        s_as[half*128 + c] = as;
        s_ad[half*128 + c] = ad;
        __syncthreads();

        float ts = 0.f, td = 0.f;
        const float* awr = s_aw + c*129;
        const float* asr = s_as + half*128;
        const float* adr = s_ad + half*128;
        for (int k = 0; k < C_; k++) {
            float w = awr[k];
            ts = fmaf(w, asr[k], ts);
            td = fmaf(w, adr[k], td);
        }
        g_tsrc[(bb*N_ + n)*C_ + c] = ts;
        g_tdst[(bb*N_ + n)*C_ + c] = td + b2;
        __syncthreads();
    }
}

// ---------------- kernel C: fused attention, 2 receivers per block ----------------
// grid = 1024 (= B * N/2), block = 256.
__global__ void __launch_bounds__(256, 2)
main_kernel(const float* __restrict__ pos, const float* __restrict__ nrm,
            const float* __restrict__ rptr, float* __restrict__ out)
{
    extern __shared__ float sh[];
    float* s_awt  = sh;                   // [c][d]  128*128 = 64 KB
    float* s_dt   = s_awt + C_*C_;        // [c][row] 128*32 = 16 KB
    float* s_sc   = s_dt + C_*32;         // [row][d] 32*128 = 16 KB
    float* s_relf = s_sc + 32*C_;         // [row][8]        = 1 KB
    float* s_pw   = s_relf + 32*8;        // 128*6
    float* s_pb   = s_pw + C_*6;          // 128
    float* s_geo  = s_pb + C_;            // 2*6
    int*   s_rows = (int*)(s_geo + 12);   // 512
    int*   s_cnt  = s_rows + 512;         // 1

    const int blk = blockIdx.x;
    const int b  = blk >> 7;
    const int i0 = (blk & 127) * 2;
    const int t  = threadIdx.x;

    for (int idx = t; idx < C_*C_; idx += 256) s_awt[idx] = g_awfT[idx];
    for (int idx = t; idx < C_*6; idx += 256)  s_pw[idx]  = g_pwf[idx];
    if (t < C_) s_pb[t] = g_pbf[t];
    if (t < 12) {
        int ii = t / 6, k = t % 6;
        s_geo[t] = (k < 3) ? pos[(b*N_ + i0 + ii)*3 + k]
                           : nrm[(b*N_ + i0 + ii)*3 + (k - 3)];
    }
    if (t == 0) s_cnt[0] = 0;
    __syncthreads();

    float rr;
    { int iv = *(const int*)rptr; rr = (iv > 0 && iv < 1000000) ? (float)iv : *rptr; }
    const float r2 = rr * rr;

    // candidate scan (j = t): receiver i0 first, then i1 (tagged)
    const float px = pos[(b*N_ + t)*3 + 0];
    const float py = pos[(b*N_ + t)*3 + 1];
    const float pz = pos[(b*N_ + t)*3 + 2];
    {
        float dx = s_geo[0]-px, dy = s_geo[1]-py, dz = s_geo[2]-pz;
        if (dx*dx + dy*dy + dz*dz <= r2) s_rows[atomicAdd(s_cnt, 1)] = t;
    }
    __syncthreads();
    {
        float dx = s_geo[6]-px, dy = s_geo[7]-py, dz = s_geo[8]-pz;
        if (dx*dx + dy*dy + dz*dz <= r2) s_rows[atomicAdd(s_cnt, 1)] = t | 256;
    }
    __syncthreads();
    const int total = s_cnt[0];

    const int d = t & 127, h = t >> 7;      // epilogue role
    const int g = t & 31,  rho = t >> 5;    // matvec role
    const int ih = i0 + h;

    const float tdst = g_tdst[(b*N_ + ih)*C_ + d];
    float pwd[6];
#pragma unroll
    for (int k = 0; k < 6; k++) pwd[k] = s_pw[d*6 + k];
    const float pbd = s_pb[d];
    const float* tsb = g_tsrc + (size_t)(b*N_)*C_;
    const float* vb  = g_v    + (size_t)(b*N_)*C_;

    float m = -1e30f, l = 0.f, o = 0.f;

    for (int base = 0; base < total; base += 32) {
        const int cnt = min(32, total - base);

        // stage relative geometry
        if (t < cnt) {
            int tag = s_rows[base + t];
            int j = tag & 255, ii = tag >> 8;
            const float* pj = pos + (b*N_ + j)*3;
            const float* nj = nrm + (b*N_ + j)*3;
            float* rf = s_relf + t*8;
            rf[0] = s_geo[ii*6+0] - pj[0];
            rf[1] = s_geo[ii*6+1] - pj[1];
            rf[2] = s_geo[ii*6+2] - pj[2];
            rf[3] = s_geo[ii*6+3] - nj[0];
            rf[4] = s_geo[ii*6+4] - nj[1];
            rf[5] = s_geo[ii*6+5] - nj[2];
        }
        __syncthreads();

        // delta^T[c][row] = relu(relf . pw' + pb')   (thread: row = t&31, c-chunk = t>>5)
        {
            int row = t & 31, cg = t >> 5;
            float rf[6];
#pragma unroll
            for (int k = 0; k < 6; k++) rf[k] = s_relf[row*8 + k];
#pragma unroll
            for (int cc = 0; cc < 16; cc++) {
                int c = cg*16 + cc;
                float dv = s_pb[c];
#pragma unroll
                for (int k = 0; k < 6; k++) dv = fmaf(rf[k], s_pw[c*6 + k], dv);
                s_dt[c*32 + row] = fmaxf(dv, 0.f);
            }
        }
        __syncthreads();

        // matvec: scores[4 rows x 4 d] per thread via packed f32x2 FMA
        unsigned long long acc[4][2];
#pragma unroll
        for (int r = 0; r < 4; r++) { acc[r][0] = 0ULL; acc[r][1] = 0ULL; }
        const float* awp = s_awt + 4*g;     // d = 4g..4g+3
        const float* dtp = s_dt + 4*rho;    // rows 4rho..4rho+3
#pragma unroll 4
        for (int c = 0; c < C_; c++) {
            ulonglong2 wa = *(const ulonglong2*)(awp + c*C_);   // 2 packed d-pairs
            float4 dl = *(const float4*)(dtp + c*32);           // 4 rows (broadcast)
            unsigned long long b0 = dup2(dl.x), b1 = dup2(dl.y);
            unsigned long long b2 = dup2(dl.z), b3 = dup2(dl.w);
            fma2(acc[0][0], wa.x, b0); fma2(acc[0][1], wa.y, b0);
            fma2(acc[1][0], wa.x, b1); fma2(acc[1][1], wa.y, b1);
            fma2(acc[2][0], wa.x, b2); fma2(acc[2][1], wa.y, b2);
            fma2(acc[3][0], wa.x, b3); fma2(acc[3][1], wa.y, b3);
        }
#pragma unroll
        for (int r = 0; r < 4; r++) {
            float4 v4;
            unpack2(acc[r][0], v4.x, v4.y);
            unpack2(acc[r][1], v4.z, v4.w);
            *(float4*)(s_sc + (4*rho + r)*C_ + 4*g) = v4;
        }
        __syncthreads();

        // epilogue: online softmax per (i_h, d)
        for (int rl = 0; rl < cnt; rl++) {
            int tag = s_rows[base + rl];
            if ((tag >> 8) != h) continue;
            int j = tag & 255;
            float z = s_sc[rl*C_ + d] + tdst - tsb[j*C_ + d];
            float s = fmaxf(z, 0.f);
            float dv = pbd;
#pragma unroll
            for (int k = 0; k < 6; k++) dv = fmaf(s_relf[rl*8 + k], pwd[k], dv);
            dv = fmaxf(dv, 0.f);
            float val = vb[j*C_ + d] + dv;
            float nm = fmaxf(m, s);
            float ea = __expf(m - nm), ep = __expf(s - nm);
            l = l*ea + ep;
            o = fmaf(o, ea, ep*val);
            m = nm;
        }
        __syncthreads();
    }

    out[(b*N_ + ih)*C_ + d] = o / l;   // self-loop guarantees l >= 1
}

// ---------------- launch ----------------
extern "C" void kernel_launch(void* const* d_in, const int* in_sizes, int n_in,
                              void* d_out, int out_size)
{
    const float* x      = (const float*)d_in[0];
    const float* pos    = (const float*)d_in[1];
    const float* normal = (const float*)d_in[2];
    const float* W_lin  = (const float*)d_in[3];
    const float* W_src  = (const float*)d_in[4];
    const float* W_dst  = (const float*)d_in[5];
    const float* pos_w  = (const float*)d_in[6];
    const float* pos_b  = (const float*)d_in[7];
    const float* pbn_g  = (const float*)d_in[8];
    const float* pbn_b  = (const float*)d_in[9];
    const float* pbn_m  = (const float*)d_in[10];
    const float* pbn_v  = (const float*)d_in[11];
    const float* attn_w = (const float*)d_in[12];
    const float* attn_b = (const float*)d_in[13];
    const float* abn_g  = (const float*)d_in[14];
    const float* abn_b  = (const float*)d_in[15];
    const float* abn_m  = (const float*)d_in[16];
    const float* abn_v  = (const float*)d_in[17];
    const float* rptr   = (const float*)d_in[18];
    float* out = (float*)d_out;

    const size_t smemB = (size_t)(3*F_*C_ + 128*129 + 128 + 256 + 256) * sizeof(float);
    const size_t smemC = (size_t)(C_*C_ + C_*32 + 32*C_ + 32*8 + C_*6 + C_ + 12) * sizeof(float)
                       + (size_t)(512 + 4) * sizeof(int);

    cudaFuncSetAttribute(precompute_kernel, cudaFuncAttributeMaxDynamicSharedMemorySize, (int)smemB);
    cudaFuncSetAttribute(main_kernel,       cudaFuncAttributeMaxDynamicSharedMemorySize, (int)smemC);
    (void)in_sizes; (void)n_in; (void)out_size;

    fold_kernel<<<128, 128>>>(pos_w, pos_b, pbn_g, pbn_b, pbn_m, pbn_v,
                              attn_w, attn_b, abn_g, abn_b, abn_m, abn_v);
    precompute_kernel<<<128, 256, smemB>>>(x, W_lin, W_src, W_dst);
    main_kernel<<<B_*N_/2, 256, smemC>>>(pos, normal, rptr, out);
}

// round 3
// speedup vs baseline: 1.7963x; 1.1274x over previous
#include <cuda_runtime.h>
#include <math.h>

#define B_ 8
#define N_ 256
#define F_ 59
#define C_ 128
#define G_ 8            // receivers per block
#define MAXROWS 1024

// ---------------- device scratch ----------------
__device__ float g_v[B_*N_*C_];
__device__ float g_tsrc[B_*N_*C_];
__device__ float g_tdst[B_*N_*C_];
__device__ float g_awf[C_*C_];    // [d][c]
__device__ float g_awfT[C_*C_];   // [c][d]
__device__ float g_pwf[C_*6];
__device__ float g_pbf[C_];
__device__ float g_b2f[C_];

// ---------------- packed f32x2 helpers ----------------
__device__ __forceinline__ unsigned long long dup2(float x) {
    unsigned long long r;
    asm("mov.b64 %0, {%1, %1};" : "=l"(r) : "r"(__float_as_uint(x)));
    return r;
}
__device__ __forceinline__ void fma2(unsigned long long& a,
                                     unsigned long long x, unsigned long long y) {
    asm("fma.rn.f32x2 %0, %1, %2, %0;" : "+l"(a) : "l"(x), "l"(y));
}
__device__ __forceinline__ void unpack2(unsigned long long a, float& lo, float& hi) {
    unsigned int l_, h_;
    asm("mov.b64 {%0, %1}, %2;" : "=r"(l_), "=r"(h_) : "l"(a));
    lo = __uint_as_float(l_); hi = __uint_as_float(h_);
}

// ---------------- kernel A: fold BN ----------------
__global__ void fold_kernel(const float* __restrict__ pos_w, const float* __restrict__ pos_b,
                            const float* __restrict__ pg, const float* __restrict__ pb,
                            const float* __restrict__ pm, const float* __restrict__ pv,
                            const float* __restrict__ attn_w, const float* __restrict__ attn_b,
                            const float* __restrict__ ag, const float* __restrict__ ab,
                            const float* __restrict__ am, const float* __restrict__ av)
{
    int c = blockIdx.x;
    int k = threadIdx.x;
    float s2 = ag[c] * rsqrtf(av[c] + 1e-5f);
    float w = attn_w[c*C_ + k] * s2;
    g_awf[c*C_ + k]  = w;
    g_awfT[k*C_ + c] = w;
    if (k == 0) {
        g_b2f[c] = attn_b[c] * s2 + ab[c] - am[c] * s2;
        float s1 = pg[c] * rsqrtf(pv[c] + 1e-5f);
        g_pbf[c] = pos_b[c] * s1 + pb[c] - pm[c] * s1;
#pragma unroll
        for (int q = 0; q < 6; q++) g_pwf[c*6 + q] = pos_w[c*6 + q] * s1;
    }
}

// ---------------- kernel B: per-node precompute ----------------
__global__ void precompute_kernel(const float* __restrict__ x,
                                  const float* __restrict__ Wl,
                                  const float* __restrict__ Ws,
                                  const float* __restrict__ Wd)
{
    extern __shared__ float sh[];
    float* s_wl = sh;
    float* s_ws = s_wl + F_*C_;
    float* s_wd = s_ws + F_*C_;
    float* s_aw = s_wd + F_*C_;       // 128*129
    float* s_x  = s_aw + 128*129;
    float* s_as = s_x + 128;
    float* s_ad = s_as + 256;

    int t = threadIdx.x;
    int bb = blockIdx.x >> 4;
    int n0 = (blockIdx.x & 15) * 16;

    for (int idx = t; idx < F_*C_; idx += 256) {
        s_wl[idx] = Wl[idx]; s_ws[idx] = Ws[idx]; s_wd[idx] = Wd[idx];
    }
    for (int idx = t; idx < C_*C_; idx += 256)
        s_aw[(idx >> 7) * 129 + (idx & 127)] = g_awf[idx];

    int half = t >> 7, c = t & 127;
    float b2 = g_b2f[c];
    __syncthreads();

    for (int it = 0; it < 8; it++) {
        int n = n0 + it*2 + half;
        if (c < F_) s_x[half*64 + c] = x[(bb*N_ + n)*F_ + c];
        __syncthreads();

        float v = 0.f, as = 0.f, ad = 0.f;
        const float* xs = s_x + half*64;
        for (int f = 0; f < F_; f++) {
            float xv = xs[f];
            v  = fmaf(xv, s_wl[c*F_+f], v);
            as = fmaf(xv, s_ws[c*F_+f], as);
            ad = fmaf(xv, s_wd[c*F_+f], ad);
        }
        g_v[(bb*N_ + n)*C_ + c] = v;
        s_as[half*128 + c] = as;
        s_ad[half*128 + c] = ad;
        __syncthreads();

        float ts = 0.f, td = 0.f;
        const float* awr = s_aw + c*129;
        const float* asr = s_as + half*128;
        const float* adr = s_ad + half*128;
        for (int k = 0; k < C_; k++) {
            float w = awr[k];
            ts = fmaf(w, asr[k], ts);
            td = fmaf(w, adr[k], td);
        }
        g_tsrc[(bb*N_ + n)*C_ + c] = ts;
        g_tdst[(bb*N_ + n)*C_ + c] = td + b2;
        __syncthreads();
    }
}

// ---------------- kernel C: fused attention, 8 receivers/block ----------------
// grid = 256, block = 256.
__global__ void __launch_bounds__(256, 2)
main_kernel(const float* __restrict__ pos, const float* __restrict__ nrm,
            const float* __restrict__ rptr, float* __restrict__ out)
{
    extern __shared__ float sh[];
    float* s_awt  = sh;                    // [c][d] 16384
    float* s_dt   = s_awt + C_*C_;         // [c][row] 4096 (aliased by scores)
    float* s_sc   = s_dt;                  // [row][d] alias of s_dt
    float* s_val  = s_dt + C_*32;          // [row][d] 4096
    float* s_relf = s_val + 32*C_;         // [row][9] 288
    float* s_pw   = s_relf + 32*9;         // 768
    float* s_pb   = s_pw + C_*6;           // 128
    float* s_td   = s_pb + C_;             // [ii][d] 1024
    float* s_geo  = s_td + G_*C_;          // [ii][6] 48
    int*   s_rows = (int*)(s_geo + G_*6);  // MAXROWS
    int*   s_roff = s_rows + MAXROWS;      // 9
    int*   s_wc   = s_roff + 9;            // 8
    int*   s_w2   = s_wc + 8;              // 8
    int*   s_tot  = s_w2 + 8;              // 1

    const int blk = blockIdx.x;
    const int b  = blk >> 5;
    const int i0 = (blk & 31) * G_;
    const int t  = threadIdx.x;
    const int wd = t >> 5, ln = t & 31;

    // stage constants
    {
        const float4* src = (const float4*)g_awfT;
        float4* dst = (float4*)s_awt;
        for (int idx = t; idx < C_*C_/4; idx += 256) dst[idx] = src[idx];
    }
    for (int idx = t; idx < C_*6; idx += 256) s_pw[idx] = g_pwf[idx];
    if (t < C_) s_pb[t] = g_pbf[t];
    for (int idx = t; idx < G_*C_; idx += 256) {
        int ii = idx >> 7, dd = idx & 127;
        s_td[idx] = g_tdst[(b*N_ + i0 + ii)*C_ + dd];
    }
    if (t < G_*6) {
        int ii = t / 6, k = t % 6;
        s_geo[t] = (k < 3) ? pos[(b*N_ + i0 + ii)*3 + k]
                           : nrm[(b*N_ + i0 + ii)*3 + (k - 3)];
    }
    if (t == 0) { *s_tot = 0; s_roff[0] = 0; }
    __syncthreads();

    float rr;
    { int iv = *(const int*)rptr; rr = (iv > 0 && iv < 1000000) ? (float)iv : *rptr; }
    const float r2 = rr * rr;

    // candidate j = t; deterministic sorted compaction per receiver
    const float px = pos[(b*N_ + t)*3 + 0];
    const float py = pos[(b*N_ + t)*3 + 1];
    const float pz = pos[(b*N_ + t)*3 + 2];
    for (int ii = 0; ii < G_; ii++) {
        float dx = s_geo[ii*6+0]-px, dy = s_geo[ii*6+1]-py, dz = s_geo[ii*6+2]-pz;
        bool pred = (dx*dx + dy*dy + dz*dz <= r2);
        unsigned mask = __ballot_sync(0xFFFFFFFFu, pred);
        if (ln == 0) s_wc[wd] = __popc(mask);
        __syncthreads();
        if (t == 0) {
            int acc = *s_tot;
            for (int w = 0; w < 8; w++) { s_w2[w] = acc; acc += s_wc[w]; }
            *s_tot = acc;
            s_roff[ii+1] = (acc < MAXROWS) ? acc : MAXROWS;
        }
        __syncthreads();
        if (pred) {
            int idx = s_w2[wd] + __popc(mask & ((1u << ln) - 1u));
            if (idx < MAXROWS) s_rows[idx] = t | (ii << 8);
        }
        __syncthreads();
    }
    const int nrows = s_roff[G_];
    const int T = (nrows + 31) & ~31;
    if (t < T - nrows) s_rows[nrows + t] = 0;   // benign padding
    __syncthreads();

    const int d = t & 127, h = t >> 7;     // (d, half) role
    const int g = t & 31,  rho = t >> 5;   // matvec role

    float pwd[6];
#pragma unroll
    for (int k = 0; k < 6; k++) pwd[k] = s_pw[d*6 + k];
    const float pbd = s_pb[d];
    const float* tsb = g_tsrc + (size_t)(b*N_)*C_;
    const float* vb  = g_v    + (size_t)(b*N_)*C_;

    float m_[4], l_[4], o_[4];
#pragma unroll
    for (int s = 0; s < 4; s++) { m_[s] = -1e30f; l_[s] = 0.f; o_[s] = 0.f; }

    for (int base = 0; base < T; base += 32) {
        // --- stage relative geometry ---
        if (t < 32) {
            int tag = s_rows[base + t];
            int j = tag & 255, ii = tag >> 8;
            const float* pj = pos + (b*N_ + j)*3;
            const float* nj = nrm + (b*N_ + j)*3;
            float* rf = s_relf + t*9;
            rf[0] = s_geo[ii*6+0] - pj[0];
            rf[1] = s_geo[ii*6+1] - pj[1];
            rf[2] = s_geo[ii*6+2] - pj[2];
            rf[3] = s_geo[ii*6+3] - nj[0];
            rf[4] = s_geo[ii*6+4] - nj[1];
            rf[5] = s_geo[ii*6+5] - nj[2];
        }
        __syncthreads();

        // --- delta^T fill: s_dt[c][row] ---
        {
            int row = t & 31, cg = t >> 5;
            float rf[6];
#pragma unroll
            for (int k = 0; k < 6; k++) rf[k] = s_relf[row*9 + k];
#pragma unroll
            for (int cc = 0; cc < 16; cc++) {
                int c = cg*16 + cc;
                float dv = s_pb[c];
#pragma unroll
                for (int k = 0; k < 6; k++) dv = fmaf(rf[k], s_pw[c*6 + k], dv);
                s_dt[c*32 + row] = fmaxf(dv, 0.f);
            }
        }
        __syncthreads();

        // --- matvec: 4 rows x 4 d per thread, packed f32x2 ---
        unsigned long long acc[4][2];
#pragma unroll
        for (int r = 0; r < 4; r++) { acc[r][0] = 0ULL; acc[r][1] = 0ULL; }
        const float* awp = s_awt + 4*g;
        const float* dtp = s_dt + 4*rho;
#pragma unroll 4
        for (int c = 0; c < C_; c++) {
            ulonglong2 wa = *(const ulonglong2*)(awp + c*C_);
            float4 dl = *(const float4*)(dtp + c*32);
            unsigned long long b0 = dup2(dl.x), b1 = dup2(dl.y);
            unsigned long long b2v = dup2(dl.z), b3 = dup2(dl.w);
            fma2(acc[0][0], wa.x, b0);  fma2(acc[0][1], wa.y, b0);
            fma2(acc[1][0], wa.x, b1);  fma2(acc[1][1], wa.y, b1);
            fma2(acc[2][0], wa.x, b2v); fma2(acc[2][1], wa.y, b2v);
            fma2(acc[3][0], wa.x, b3);  fma2(acc[3][1], wa.y, b3);
        }
        __syncthreads();   // all s_dt reads complete before score overwrite (alias)

#pragma unroll
        for (int r = 0; r < 4; r++) {
            float4 v4;
            unpack2(acc[r][0], v4.x, v4.y);
            unpack2(acc[r][1], v4.z, v4.w);
            *(float4*)(s_sc + (4*rho + r)*C_ + 4*g) = v4;
        }
        __syncthreads();

        // --- E1: batched gather + score/val staging (high MLP) ---
#pragma unroll
        for (int kb = 0; kb < 2; kb++) {
            float tsv[8], vvv[8]; int tg[8];
#pragma unroll
            for (int k = 0; k < 8; k++) {
                int r = h + 2*(kb*8 + k);
                int tag = s_rows[base + r];
                tg[k] = tag;
                int j = tag & 255;
                tsv[k] = tsb[j*C_ + d];
                vvv[k] = vb[j*C_ + d];
            }
#pragma unroll
            for (int k = 0; k < 8; k++) {
                int r = h + 2*(kb*8 + k);
                int ii = tg[k] >> 8;
                float z = s_sc[r*C_ + d] + s_td[ii*C_ + d] - tsv[k];
                float scv = fmaxf(z, 0.f);
                float dv = pbd;
#pragma unroll
                for (int kk = 0; kk < 6; kk++)
                    dv = fmaf(s_relf[r*9 + kk], pwd[kk], dv);
                dv = fmaxf(dv, 0.f);
                s_sc[r*C_ + d]  = scv;
                s_val[r*C_ + d] = vvv[k] + dv;
            }
        }
        __syncthreads();

        // --- E2: online softmax over exact per-receiver ranges ---
#pragma unroll
        for (int s = 0; s < 4; s++) {
            int ii = h + 2*s;
            int lo = s_roff[ii]   - base; if (lo < 0)  lo = 0;
            int hi = s_roff[ii+1] - base; if (hi > 32) hi = 32;
            for (int r = lo; r < hi; r++) {
                float scv = s_sc[r*C_ + d];
                float val = s_val[r*C_ + d];
                float nm = fmaxf(m_[s], scv);
                float ea = __expf(m_[s] - nm), ep = __expf(scv - nm);
                l_[s] = l_[s]*ea + ep;
                o_[s] = fmaf(o_[s], ea, ep*val);
                m_[s] = nm;
            }
        }
        __syncthreads();
    }

#pragma unroll
    for (int s = 0; s < 4; s++) {
        int ii = h + 2*s;
        out[(b*N_ + i0 + ii)*C_ + d] = o_[s] / l_[s];
    }
}

// ---------------- launch ----------------
extern "C" void kernel_launch(void* const* d_in, const int* in_sizes, int n_in,
                              void* d_out, int out_size)
{
    const float* x      = (const float*)d_in[0];
    const float* pos    = (const float*)d_in[1];
    const float* normal = (const float*)d_in[2];
    const float* W_lin  = (const float*)d_in[3];
    const float* W_src  = (const float*)d_in[4];
    const float* W_dst  = (const float*)d_in[5];
    const float* pos_w  = (const float*)d_in[6];
    const float* pos_b  = (const float*)d_in[7];
    const float* pbn_g  = (const float*)d_in[8];
    const float* pbn_b  = (const float*)d_in[9];
    const float* pbn_m  = (const float*)d_in[10];
    const float* pbn_v  = (const float*)d_in[11];
    const float* attn_w = (const float*)d_in[12];
    const float* attn_b = (const float*)d_in[13];
    const float* abn_g  = (const float*)d_in[14];
    const float* abn_b  = (const float*)d_in[15];
    const float* abn_m  = (const float*)d_in[16];
    const float* abn_v  = (const float*)d_in[17];
    const float* rptr   = (const float*)d_in[18];
    float* out = (float*)d_out;

    const size_t smemB = (size_t)(3*F_*C_ + 128*129 + 128 + 256 + 256) * sizeof(float);
    const size_t smemC = (size_t)(C_*C_ + C_*32 + 32*C_ + 32*9 + C_*6 + C_ + G_*C_ + G_*6) * sizeof(float)
                       + (size_t)(MAXROWS + 9 + 8 + 8 + 4) * sizeof(int);

    cudaFuncSetAttribute(precompute_kernel, cudaFuncAttributeMaxDynamicSharedMemorySize, (int)smemB);
    cudaFuncSetAttribute(main_kernel,       cudaFuncAttributeMaxDynamicSharedMemorySize, (int)smemC);
    (void)in_sizes; (void)n_in; (void)out_size;

    fold_kernel<<<128, 128>>>(pos_w, pos_b, pbn_g, pbn_b, pbn_m, pbn_v,
                              attn_w, attn_b, abn_g, abn_b, abn_m, abn_v);
    precompute_kernel<<<128, 256, smemB>>>(x, W_lin, W_src, W_dst);
    main_kernel<<<B_*N_/G_, 256, smemC>>>(pos, normal, rptr, out);
}